// round 14
// baseline (speedup 1.0000x reference)
#include <cuda_runtime.h>
#include <cstdint>

// ---------------------------------------------------------------------------
// R13: R11 structure + 3 CTAs/SM for kernel A.
//  Kernel A (qkv_attn): one CTA per batch element, 3 CTAs/SM (41KB smem).
//    No x smem: A-fragments read from global per GEMM (L1/L2 served).
//    Double-buffered weight staging (Wk staged during Q-GEMM, Wv during
//    K-GEMM); K stored into the dead Wk buffer with an XOR swizzle;
//    streaming causal attention; O written as tf32 A-frags to scratch.
//  Kernel B (proj): exact R11 proj — A-frags via LDG.128 from scratch,
//    Wp staged once at stride 136, scalar B-frag LDS.
// ---------------------------------------------------------------------------

namespace {

constexpr int WAST = 40;                       // W/V/K buffer stride (words)
constexpr int BA_OFF = 0;
constexpr int BB_OFF = 128 * WAST;             // 5120
constexpr int SMEMA_WORDS = BB_OFF + 128 * WAST;   // 10240 words = 40960 B
constexpr unsigned SMEMA_BYTES = SMEMA_WORDS * 4;  // 3 CTAs/SM

constexpr int PST = 136;                        // Wp stage stride (proj)
constexpr int SMEMB_WORDS = 128 * PST;          // 17408 words = 69632 B
constexpr unsigned SMEMB_BYTES = SMEMB_WORDS * 4;

// O scratch in tf32 A-fragment order: [(b*8+w)*16 + kt][lane*4 + j]
__device__ uint32_t g_scratch[4096ull * 16 * 8 * 128];

__device__ __forceinline__ uint32_t f2tf32(float f) {
  uint32_t r;
  asm("cvt.rna.tf32.f32 %0, %1;" : "=r"(r) : "f"(f));
  return r;
}

__device__ __forceinline__ void mma8(float& d0, float& d1, float& d2, float& d3,
                                     uint32_t a0, uint32_t a1, uint32_t a2, uint32_t a3,
                                     uint32_t b0, uint32_t b1) {
  asm volatile(
      "mma.sync.aligned.m16n8k8.row.col.f32.tf32.tf32.f32 "
      "{%0,%1,%2,%3},{%4,%5,%6,%7},{%8,%9},{%0,%1,%2,%3};"
      : "+f"(d0), "+f"(d1), "+f"(d2), "+f"(d3)
      : "r"(a0), "r"(a1), "r"(a2), "r"(a3), "r"(b0), "r"(b1));
}

// m16n8 C-layout tile -> m16k8 A-layout tile (tf32). 8 shuffles, warp-uniform.
__device__ __forceinline__ void c2a(float c0, float c1, float c2, float c3,
                                    uint32_t a[4]) {
  int lane = threadIdx.x & 31;
  int qi = lane & 3;
  int s1 = (lane & ~3) | (qi >> 1);
  int s2 = s1 + 2;
  float t0 = __shfl_sync(0xffffffffu, c0, s1);
  float t1 = __shfl_sync(0xffffffffu, c1, s1);
  float t2 = __shfl_sync(0xffffffffu, c2, s1);
  float t3 = __shfl_sync(0xffffffffu, c3, s1);
  float u0 = __shfl_sync(0xffffffffu, c0, s2);
  float u1 = __shfl_sync(0xffffffffu, c1, s2);
  float u2 = __shfl_sync(0xffffffffu, c2, s2);
  float u3 = __shfl_sync(0xffffffffu, c3, s2);
  bool odd = (qi & 1);
  a[0] = f2tf32(odd ? t1 : t0);
  a[1] = f2tf32(odd ? t3 : t2);
  a[2] = f2tf32(odd ? u1 : u0);
  a[3] = f2tf32(odd ? u3 : u2);
}

// Stage one [128 x 32] fp32 weight matrix into smem, row stride 40 (tf32).
__device__ __forceinline__ void stage_w(uint32_t* dst, const float* src, int tid) {
  const float4* s4 = reinterpret_cast<const float4*>(src);
  #pragma unroll
  for (int i = 0; i < 4; i++) {
    int v = tid + i * 256;
    float4 f = s4[v];
    uint32_t* p = dst + (v >> 3) * WAST + ((v & 7) << 2);
    p[0] = f2tf32(f.x); p[1] = f2tf32(f.y); p[2] = f2tf32(f.z); p[3] = f2tf32(f.w);
  }
}

// acc[4][4] += x-rows(row0/row1, from GLOBAL) @ Wbuf(128x32, stride 40)
__device__ __forceinline__ void gemm_xg_w(const float* xr0p, const float* xr1p,
                                          const uint32_t* Wb, int qi, int g,
                                          float acc[4][4]) {
  #pragma unroll
  for (int kt = 0; kt < 16; kt++) {
    int c = kt * 8 + qi;
    uint32_t a0 = f2tf32(__ldg(xr0p + c));
    uint32_t a1 = f2tf32(__ldg(xr1p + c));
    uint32_t a2 = f2tf32(__ldg(xr0p + c + 4));
    uint32_t a3 = f2tf32(__ldg(xr1p + c + 4));
    int brow = c * WAST;
    #pragma unroll
    for (int nt = 0; nt < 4; nt++) {
      int boff = brow + nt * 8 + g;
      mma8(acc[nt][0], acc[nt][1], acc[nt][2], acc[nt][3],
           a0, a1, a2, a3, Wb[boff], Wb[boff + 4 * WAST]);
    }
  }
}

// ============================ Kernel A ====================================
__global__ __launch_bounds__(256, 3)
void qkv_attn_kernel(const float* __restrict__ x,
                     const float* __restrict__ Wq, const float* __restrict__ bq,
                     const float* __restrict__ Wk, const float* __restrict__ bk,
                     const float* __restrict__ Wv, const float* __restrict__ bv) {
  extern __shared__ uint32_t sm[];
  uint32_t* BA = sm + BA_OFF;   // Wq stage -> Wv stage -> V
  uint32_t* BB = sm + BB_OFF;   // Wk stage -> K (XOR-swizzled)

  const int tid = threadIdx.x;
  const int lane = tid & 31;
  const int w = tid >> 5;
  const int g = lane >> 2;
  const int qi = lane & 3;
  const int b = blockIdx.x;
  const int row0 = w * 16 + g;
  const int row1 = row0 + 8;
  const int ksw = g << 2;   // K swizzle: row&7 == g for rows 16w+g and +8

  const float* xr0p = x + (size_t)b * 16384 + row0 * 128;
  const float* xr1p = x + (size_t)b * 16384 + row1 * 128;

  const int nt_lim = 2 * w + 1;
  const float scale = 0.088388347648318447f;  // 128^-0.5 (CONTEXT_SIZE scaling)
  uint32_t* og = g_scratch + ((size_t)b * 8 + w) * 2048 + lane * 4;

  for (int h = 0; h < 4; h++) {
    __syncthreads();                       // sync0: prior attention K/V reads done

    stage_w(BA, Wq + h * 4096, tid);
    __syncthreads();                       // sync1: Wq visible

    // ---- Q = x @ Wq_h ----
    float acc[4][4];
    #pragma unroll
    for (int nt = 0; nt < 4; nt++)
      { acc[nt][0] = 0.f; acc[nt][1] = 0.f; acc[nt][2] = 0.f; acc[nt][3] = 0.f; }
    gemm_xg_w(xr0p, xr1p, BA, qi, g, acc);
    uint32_t qa[4][4];
    #pragma unroll
    for (int nt = 0; nt < 4; nt++) {
      int c = nt * 8 + 2 * qi;
      float2 b2 = *reinterpret_cast<const float2*>(bq + h * 32 + c);
      c2a((acc[nt][0] + b2.x) * scale, (acc[nt][1] + b2.y) * scale,
          (acc[nt][2] + b2.x) * scale, (acc[nt][3] + b2.y) * scale, qa[nt]);
    }
    stage_w(BB, Wk + h * 4096, tid);       // overlap: Wk stage after Q-GEMM
    __syncthreads();                       // sync2: Wk visible, all Q-GEMMs done

    // ---- K = x @ Wk_h ----
    #pragma unroll
    for (int nt = 0; nt < 4; nt++)
      { acc[nt][0] = 0.f; acc[nt][1] = 0.f; acc[nt][2] = 0.f; acc[nt][3] = 0.f; }
    gemm_xg_w(xr0p, xr1p, BB, qi, g, acc);
    float kv[4][4];
    #pragma unroll
    for (int nt = 0; nt < 4; nt++) {
      int c = nt * 8 + 2 * qi;
      float2 b2 = *reinterpret_cast<const float2*>(bk + h * 32 + c);
      kv[nt][0] = acc[nt][0] + b2.x; kv[nt][1] = acc[nt][1] + b2.y;
      kv[nt][2] = acc[nt][2] + b2.x; kv[nt][3] = acc[nt][3] + b2.y;
    }
    stage_w(BA, Wv + h * 4096, tid);       // overlap: Wv stage (Wq dead)
    __syncthreads();                       // sync3: Wv visible, all K-GEMMs done

    // ---- V = x @ Wv_h ----
    #pragma unroll
    for (int nt = 0; nt < 4; nt++)
      { acc[nt][0] = 0.f; acc[nt][1] = 0.f; acc[nt][2] = 0.f; acc[nt][3] = 0.f; }
    gemm_xg_w(xr0p, xr1p, BA, qi, g, acc);
    // store K into BB (Wk dead; all K-GEMM reads finished at sync3), swizzled
    #pragma unroll
    for (int nt = 0; nt < 4; nt++) {
      int c = nt * 8 + 2 * qi;
      BB[row0 * WAST + (c ^ ksw)]       = f2tf32(kv[nt][0]);
      BB[row0 * WAST + ((c + 1) ^ ksw)] = f2tf32(kv[nt][1]);
      BB[row1 * WAST + (c ^ ksw)]       = f2tf32(kv[nt][2]);
      BB[row1 * WAST + ((c + 1) ^ ksw)] = f2tf32(kv[nt][3]);
    }
    __syncthreads();                       // sync4: all V-GEMMs done (Wv dead)
    // store V into BA
    #pragma unroll
    for (int nt = 0; nt < 4; nt++) {
      int c = nt * 8 + 2 * qi;
      float2 b2 = *reinterpret_cast<const float2*>(bv + h * 32 + c);
      BA[row0 * WAST + c]     = f2tf32(acc[nt][0] + b2.x);
      BA[row0 * WAST + c + 1] = f2tf32(acc[nt][1] + b2.y);
      BA[row1 * WAST + c]     = f2tf32(acc[nt][2] + b2.x);
      BA[row1 * WAST + c + 1] = f2tf32(acc[nt][3] + b2.y);
    }
    __syncthreads();                       // sync5: K (BB) and V (BA) visible

    // ---- streaming causal attention ----
    float oacc[4][4];
    #pragma unroll
    for (int nt = 0; nt < 4; nt++)
      { oacc[nt][0] = 0.f; oacc[nt][1] = 0.f; oacc[nt][2] = 0.f; oacc[nt][3] = 0.f; }
    float sum0 = 0.f, sum1 = 0.f;

    #pragma unroll
    for (int nt = 0; nt < 16; nt++) {
      if (nt <= nt_lim) {
        float s0 = 0.f, s1 = 0.f, s2 = 0.f, s3 = 0.f;
        int krow = (nt * 8 + g) * WAST;
        #pragma unroll
        for (int kt = 0; kt < 4; kt++) {
          uint32_t b0 = BB[krow + ((kt * 8 + qi) ^ ksw)];
          uint32_t b1 = BB[krow + ((kt * 8 + qi + 4) ^ ksw)];
          mma8(s0, s1, s2, s3,
               qa[kt][0], qa[kt][1], qa[kt][2], qa[kt][3], b0, b1);
        }
        int c = nt * 8 + 2 * qi;
        float p0 = (c     > row0 - w * 16 + row0 - row0 + row0) ? 0.f : __expf(s0);
        // (see below: correct masks)
        p0 = (c     > row0) ? 0.f : __expf(s0);
        float p1 = (c + 1 > row0) ? 0.f : __expf(s1);
        float p2 = (c     > row1) ? 0.f : __expf(s2);
        float p3 = (c + 1 > row1) ? 0.f : __expf(s3);
        sum0 += p0 + p1;
        sum1 += p2 + p3;

        uint32_t pa[4];
        c2a(p0, p1, p2, p3, pa);
        int brow = (nt * 8 + qi) * WAST;
        #pragma unroll
        for (int ntv = 0; ntv < 4; ntv++) {
          int boff = brow + ntv * 8 + g;
          mma8(oacc[ntv][0], oacc[ntv][1], oacc[ntv][2], oacc[ntv][3],
               pa[0], pa[1], pa[2], pa[3], BA[boff], BA[boff + 4 * WAST]);
        }
      }
    }

    sum0 += __shfl_xor_sync(0xffffffffu, sum0, 1);
    sum0 += __shfl_xor_sync(0xffffffffu, sum0, 2);
    sum1 += __shfl_xor_sync(0xffffffffu, sum1, 1);
    sum1 += __shfl_xor_sync(0xffffffffu, sum1, 2);
    float inv0 = __fdividef(1.0f, sum0);
    float inv1 = __fdividef(1.0f, sum1);

    // normalize -> A-layout tf32 -> coalesced STG.128 to scratch
    #pragma unroll
    for (int nt = 0; nt < 4; nt++) {
      uint32_t oa[4];
      c2a(oacc[nt][0] * inv0, oacc[nt][1] * inv0,
          oacc[nt][2] * inv1, oacc[nt][3] * inv1, oa);
      *reinterpret_cast<uint4*>(og + (h * 4 + nt) * 128) =
          make_uint4(oa[0], oa[1], oa[2], oa[3]);
    }
  }
}

// ============================ Kernel B ====================================
// out = O @ Wp + bp.  A-frags straight from scratch via LDG.128; Wp staged once.
__global__ __launch_bounds__(256, 2)
void proj_kernel(const float* __restrict__ Wp, const float* __restrict__ bp,
                 float* __restrict__ out) {
  extern __shared__ uint32_t sm[];   // Wp, stride 136

  const int tid = threadIdx.x;
  const int lane = tid & 31;
  const int w = tid >> 5;
  const int g = lane >> 2;
  const int qi = lane & 3;
  const int b = blockIdx.x;
  const int row0 = w * 16 + g;
  const int row1 = row0 + 8;

  // stage Wp (tf32, stride 136)
  {
    const float4* wg = reinterpret_cast<const float4*>(Wp);
    #pragma unroll
    for (int i = 0; i < 16; i++) {
      int v = tid + i * 256;
      float4 f = wg[v];
      uint32_t* p = sm + (v >> 5) * PST + ((v & 31) << 2);
      p[0] = f2tf32(f.x); p[1] = f2tf32(f.y); p[2] = f2tf32(f.z); p[3] = f2tf32(f.w);
    }
  }

  // A-frags: 16 coalesced LDG.128 from scratch
  uint32_t A[16][4];
  const uint32_t* ab = g_scratch + ((size_t)b * 8 + w) * 2048 + lane * 4;
  #pragma unroll
  for (int kt = 0; kt < 16; kt++) {
    uint4 v = *reinterpret_cast<const uint4*>(ab + kt * 128);
    A[kt][0] = v.x; A[kt][1] = v.y; A[kt][2] = v.z; A[kt][3] = v.w;
  }
  __syncthreads();

  float* og = out + (size_t)b * 16384;
  #pragma unroll
  for (int half = 0; half < 2; half++) {
    float acc[8][4];
    #pragma unroll
    for (int nt8 = 0; nt8 < 8; nt8++) {
      int c = (half * 8 + nt8) * 8 + 2 * qi;
      float2 bp2 = *reinterpret_cast<const float2*>(bp + c);
      acc[nt8][0] = bp2.x; acc[nt8][1] = bp2.y; acc[nt8][2] = bp2.x; acc[nt8][3] = bp2.y;
    }
    #pragma unroll
    for (int kt = 0; kt < 16; kt++) {
      int brow = (kt * 8 + qi) * PST;
      #pragma unroll
      for (int nt8 = 0; nt8 < 8; nt8++) {
        int boff = brow + (half * 8 + nt8) * 8 + g;
        mma8(acc[nt8][0], acc[nt8][1], acc[nt8][2], acc[nt8][3],
             A[kt][0], A[kt][1], A[kt][2], A[kt][3],
             sm[boff], sm[boff + 4 * PST]);
      }
    }
    #pragma unroll
    for (int nt8 = 0; nt8 < 8; nt8++) {
      int c = (half * 8 + nt8) * 8 + 2 * qi;
      *reinterpret_cast<float2*>(og + row0 * 128 + c) = make_float2(acc[nt8][0], acc[nt8][1]);
      *reinterpret_cast<float2*>(og + row1 * 128 + c) = make_float2(acc[nt8][2], acc[nt8][3]);
    }
  }
}

}  // namespace

extern "C" void kernel_launch(void* const* d_in, const int* in_sizes, int n_in,
                              void* d_out, int out_size) {
  const float* x  = (const float*)d_in[0];
  const float* Wq = (const float*)d_in[1];
  const float* bq = (const float*)d_in[2];
  const float* Wk = (const float*)d_in[3];
  const float* bk = (const float*)d_in[4];
  const float* Wv = (const float*)d_in[5];
  const float* bv = (const float*)d_in[6];
  const float* Wp = (const float*)d_in[7];
  const float* bp = (const float*)d_in[8];
  float* out = (float*)d_out;

  int batches = in_sizes[0] / (128 * 128);  // 4096

  cudaFuncSetAttribute(qkv_attn_kernel,
                       cudaFuncAttributeMaxDynamicSharedMemorySize, SMEMA_BYTES);
  cudaFuncSetAttribute(proj_kernel,
                       cudaFuncAttributeMaxDynamicSharedMemorySize, SMEMB_BYTES);

  qkv_attn_kernel<<<batches, 256, SMEMA_BYTES>>>(x, Wq, bq, Wk, bk, Wv, bv);
  proj_kernel<<<batches, 256, SMEMB_BYTES>>>(Wp, bp, out);
}

// round 15
// speedup vs baseline: 1.2706x; 1.2706x over previous
#include <cuda_runtime.h>
#include <cstdint>

// ---------------------------------------------------------------------------
// R14: kernel A = R11 verbatim (best measured); proj rebuilt for 3 CTAs/SM.
//  Kernel A (qkv_attn): one CTA per batch element, 2 CTAs/SM.
//    x staged in XOR-swizzled smem; double-buffered weight staging; K stored
//    into the dead Wk buffer (XOR swizzle); streaming causal attention;
//    O written as tf32 A-frags to scratch (STG.128, thread-linear).
//  Kernel B (proj): 3 CTAs/SM (85 regs). A-frags streamed per-kt from
//    scratch with manual double buffering (read twice, once per half);
//    Wp staged once at stride 136; out = O @ Wp + bp.
// ---------------------------------------------------------------------------

namespace {

constexpr int WAST = 40;                       // W/V/K buffer stride (words)
constexpr int B1A_OFF = 128 * 128;             // after swizzled x (16384 words)
constexpr int B1B_OFF = B1A_OFF + 128 * WAST;  // 21504
constexpr int SMEMA_WORDS = B1B_OFF + 128 * WAST;  // 26624 words = 106496 B
constexpr unsigned SMEMA_BYTES = SMEMA_WORDS * 4;

constexpr int PST = 136;                        // Wp stage stride (proj)
constexpr int SMEMB_WORDS = 128 * PST;          // 17408 words = 69632 B
constexpr unsigned SMEMB_BYTES = SMEMB_WORDS * 4;

// O scratch in tf32 A-fragment order: [(b*8+w)*16 + kt][lane*4 + j]
__device__ uint32_t g_scratch[4096ull * 16 * 8 * 128];

__device__ __forceinline__ uint32_t f2tf32(float f) {
  uint32_t r;
  asm("cvt.rna.tf32.f32 %0, %1;" : "=r"(r) : "f"(f));
  return r;
}

__device__ __forceinline__ void mma8(float& d0, float& d1, float& d2, float& d3,
                                     uint32_t a0, uint32_t a1, uint32_t a2, uint32_t a3,
                                     uint32_t b0, uint32_t b1) {
  asm volatile(
      "mma.sync.aligned.m16n8k8.row.col.f32.tf32.tf32.f32 "
      "{%0,%1,%2,%3},{%4,%5,%6,%7},{%8,%9},{%0,%1,%2,%3};"
      : "+f"(d0), "+f"(d1), "+f"(d2), "+f"(d3)
      : "r"(a0), "r"(a1), "r"(a2), "r"(a3), "r"(b0), "r"(b1));
}

// m16n8 C-layout tile -> m16k8 A-layout tile (tf32). 8 shuffles, warp-uniform.
__device__ __forceinline__ void c2a(float c0, float c1, float c2, float c3,
                                    uint32_t a[4]) {
  int lane = threadIdx.x & 31;
  int qi = lane & 3;
  int s1 = (lane & ~3) | (qi >> 1);
  int s2 = s1 + 2;
  float t0 = __shfl_sync(0xffffffffu, c0, s1);
  float t1 = __shfl_sync(0xffffffffu, c1, s1);
  float t2 = __shfl_sync(0xffffffffu, c2, s1);
  float t3 = __shfl_sync(0xffffffffu, c3, s1);
  float u0 = __shfl_sync(0xffffffffu, c0, s2);
  float u1 = __shfl_sync(0xffffffffu, c1, s2);
  float u2 = __shfl_sync(0xffffffffu, c2, s2);
  float u3 = __shfl_sync(0xffffffffu, c3, s2);
  bool odd = (qi & 1);
  a[0] = f2tf32(odd ? t1 : t0);
  a[1] = f2tf32(odd ? t3 : t2);
  a[2] = f2tf32(odd ? u1 : u0);
  a[3] = f2tf32(odd ? u3 : u2);
}

// Stage [128 x 128] fp32 -> XOR-swizzled tf32 smem. word(t,d)=t*128+(d^((t&7)<<2))
__device__ __forceinline__ void stage_sw128(uint32_t* dst, const float* src, int tid) {
  const float4* s4 = reinterpret_cast<const float4*>(src);
  #pragma unroll
  for (int i = 0; i < 16; i++) {
    int v = tid + i * 256;
    float4 f = s4[v];
    int t = v >> 5;
    int d0 = (v & 31) << 2;
    uint32_t* p = dst + t * 128 + (d0 ^ ((t & 7) << 2));
    p[0] = f2tf32(f.x); p[1] = f2tf32(f.y); p[2] = f2tf32(f.z); p[3] = f2tf32(f.w);
  }
}

// Stage one [128 x 32] fp32 weight matrix into smem, row stride 40 (tf32).
__device__ __forceinline__ void stage_w(uint32_t* dst, const float* src, int tid) {
  const float4* s4 = reinterpret_cast<const float4*>(src);
  #pragma unroll
  for (int i = 0; i < 4; i++) {
    int v = tid + i * 256;
    float4 f = s4[v];
    uint32_t* p = dst + (v >> 3) * WAST + ((v & 7) << 2);
    p[0] = f2tf32(f.x); p[1] = f2tf32(f.y); p[2] = f2tf32(f.z); p[3] = f2tf32(f.w);
  }
}

// acc[4][4] += XS(16 rows of warp) @ Wbuf(128x32, stride 40)
__device__ __forceinline__ void gemm_x_w(const uint32_t* XS, const uint32_t* Wb,
                                         int xr0, int xr1, int xsw, int qi, int g,
                                         float acc[4][4]) {
  #pragma unroll
  for (int kt = 0; kt < 16; kt++) {
    int c = kt * 8 + qi;
    uint32_t a0 = XS[xr0 + (c ^ xsw)];
    uint32_t a1 = XS[xr1 + (c ^ xsw)];
    uint32_t a2 = XS[xr0 + ((c + 4) ^ xsw)];
    uint32_t a3 = XS[xr1 + ((c + 4) ^ xsw)];
    int brow = c * WAST;
    #pragma unroll
    for (int nt = 0; nt < 4; nt++) {
      int boff = brow + nt * 8 + g;
      mma8(acc[nt][0], acc[nt][1], acc[nt][2], acc[nt][3],
           a0, a1, a2, a3, Wb[boff], Wb[boff + 4 * WAST]);
    }
  }
}

// ============================ Kernel A ====================================
__global__ __launch_bounds__(256, 2)
void qkv_attn_kernel(const float* __restrict__ x,
                     const float* __restrict__ Wq, const float* __restrict__ bq,
                     const float* __restrict__ Wk, const float* __restrict__ bk,
                     const float* __restrict__ Wv, const float* __restrict__ bv) {
  extern __shared__ uint32_t sm[];
  uint32_t* XS = sm;
  uint32_t* BA = sm + B1A_OFF;   // Wq stage -> Wv stage -> V
  uint32_t* BB = sm + B1B_OFF;   // Wk stage -> K (XOR-swizzled)

  const int tid = threadIdx.x;
  const int lane = tid & 31;
  const int w = tid >> 5;
  const int g = lane >> 2;
  const int qi = lane & 3;
  const int b = blockIdx.x;
  const int row0 = w * 16 + g;
  const int row1 = row0 + 8;
  const int xr0 = row0 * 128, xr1 = row1 * 128, xsw = g << 2;
  const int ksw = g << 2;

  stage_sw128(XS, x + (size_t)b * 16384, tid);

  const int nt_lim = 2 * w + 1;
  const float scale = 0.088388347648318447f;  // 128^-0.5 (CONTEXT_SIZE scaling)
  uint32_t* og = g_scratch + ((size_t)b * 8 + w) * 2048 + lane * 4;

  for (int h = 0; h < 4; h++) {
    __syncthreads();                       // sync0: prior attention K/V reads done

    stage_w(BA, Wq + h * 4096, tid);
    __syncthreads();                       // sync1: Wq visible

    // ---- Q = x @ Wq_h ----
    float acc[4][4];
    #pragma unroll
    for (int nt = 0; nt < 4; nt++)
      { acc[nt][0] = 0.f; acc[nt][1] = 0.f; acc[nt][2] = 0.f; acc[nt][3] = 0.f; }
    gemm_x_w(XS, BA, xr0, xr1, xsw, qi, g, acc);
    uint32_t qa[4][4];
    #pragma unroll
    for (int nt = 0; nt < 4; nt++) {
      int c = nt * 8 + 2 * qi;
      float2 b2 = *reinterpret_cast<const float2*>(bq + h * 32 + c);
      c2a((acc[nt][0] + b2.x) * scale, (acc[nt][1] + b2.y) * scale,
          (acc[nt][2] + b2.x) * scale, (acc[nt][3] + b2.y) * scale, qa[nt]);
    }
    stage_w(BB, Wk + h * 4096, tid);       // overlap: Wk stage after Q-GEMM
    __syncthreads();                       // sync2: Wk visible, all Q-GEMMs done

    // ---- K = x @ Wk_h ----
    #pragma unroll
    for (int nt = 0; nt < 4; nt++)
      { acc[nt][0] = 0.f; acc[nt][1] = 0.f; acc[nt][2] = 0.f; acc[nt][3] = 0.f; }
    gemm_x_w(XS, BB, xr0, xr1, xsw, qi, g, acc);
    float kv[4][4];
    #pragma unroll
    for (int nt = 0; nt < 4; nt++) {
      int c = nt * 8 + 2 * qi;
      float2 b2 = *reinterpret_cast<const float2*>(bk + h * 32 + c);
      kv[nt][0] = acc[nt][0] + b2.x; kv[nt][1] = acc[nt][1] + b2.y;
      kv[nt][2] = acc[nt][2] + b2.x; kv[nt][3] = acc[nt][3] + b2.y;
    }
    stage_w(BA, Wv + h * 4096, tid);       // overlap: Wv stage (Wq dead)
    __syncthreads();                       // sync3: Wv visible, all K-GEMMs done

    // ---- V = x @ Wv_h ----
    #pragma unroll
    for (int nt = 0; nt < 4; nt++)
      { acc[nt][0] = 0.f; acc[nt][1] = 0.f; acc[nt][2] = 0.f; acc[nt][3] = 0.f; }
    gemm_x_w(XS, BA, xr0, xr1, xsw, qi, g, acc);
    // store K into BB (Wk dead; all K-GEMM reads finished at sync3), swizzled
    #pragma unroll
    for (int nt = 0; nt < 4; nt++) {
      int c = nt * 8 + 2 * qi;
      BB[row0 * WAST + (c ^ ksw)]       = f2tf32(kv[nt][0]);
      BB[row0 * WAST + ((c + 1) ^ ksw)] = f2tf32(kv[nt][1]);
      BB[row1 * WAST + (c ^ ksw)]       = f2tf32(kv[nt][2]);
      BB[row1 * WAST + ((c + 1) ^ ksw)] = f2tf32(kv[nt][3]);
    }
    __syncthreads();                       // sync4: all V-GEMMs done (Wv dead)
    // store V into BA
    #pragma unroll
    for (int nt = 0; nt < 4; nt++) {
      int c = nt * 8 + 2 * qi;
      float2 b2 = *reinterpret_cast<const float2*>(bv + h * 32 + c);
      BA[row0 * WAST + c]     = f2tf32(acc[nt][0] + b2.x);
      BA[row0 * WAST + c + 1] = f2tf32(acc[nt][1] + b2.y);
      BA[row1 * WAST + c]     = f2tf32(acc[nt][2] + b2.x);
      BA[row1 * WAST + c + 1] = f2tf32(acc[nt][3] + b2.y);
    }
    __syncthreads();                       // sync5: K (BB) and V (BA) visible

    // ---- streaming causal attention ----
    float oacc[4][4];
    #pragma unroll
    for (int nt = 0; nt < 4; nt++)
      { oacc[nt][0] = 0.f; oacc[nt][1] = 0.f; oacc[nt][2] = 0.f; oacc[nt][3] = 0.f; }
    float sum0 = 0.f, sum1 = 0.f;

    #pragma unroll
    for (int nt = 0; nt < 16; nt++) {
      if (nt <= nt_lim) {
        float s0 = 0.f, s1 = 0.f, s2 = 0.f, s3 = 0.f;
        int krow = (nt * 8 + g) * WAST;
        #pragma unroll
        for (int kt = 0; kt < 4; kt++) {
          uint32_t b0 = BB[krow + ((kt * 8 + qi) ^ ksw)];
          uint32_t b1 = BB[krow + ((kt * 8 + qi + 4) ^ ksw)];
          mma8(s0, s1, s2, s3,
               qa[kt][0], qa[kt][1], qa[kt][2], qa[kt][3], b0, b1);
        }
        int c = nt * 8 + 2 * qi;
        float p0 = (c     > row0) ? 0.f : __expf(s0);
        float p1 = (c + 1 > row0) ? 0.f : __expf(s1);
        float p2 = (c     > row1) ? 0.f : __expf(s2);
        float p3 = (c + 1 > row1) ? 0.f : __expf(s3);
        sum0 += p0 + p1;
        sum1 += p2 + p3;

        uint32_t pa[4];
        c2a(p0, p1, p2, p3, pa);
        int brow = (nt * 8 + qi) * WAST;
        #pragma unroll
        for (int ntv = 0; ntv < 4; ntv++) {
          int boff = brow + ntv * 8 + g;
          mma8(oacc[ntv][0], oacc[ntv][1], oacc[ntv][2], oacc[ntv][3],
               pa[0], pa[1], pa[2], pa[3], BA[boff], BA[boff + 4 * WAST]);
        }
      }
    }

    sum0 += __shfl_xor_sync(0xffffffffu, sum0, 1);
    sum0 += __shfl_xor_sync(0xffffffffu, sum0, 2);
    sum1 += __shfl_xor_sync(0xffffffffu, sum1, 1);
    sum1 += __shfl_xor_sync(0xffffffffu, sum1, 2);
    float inv0 = __fdividef(1.0f, sum0);
    float inv1 = __fdividef(1.0f, sum1);

    // normalize -> A-layout tf32 -> coalesced STG.128 to scratch
    #pragma unroll
    for (int nt = 0; nt < 4; nt++) {
      uint32_t oa[4];
      c2a(oacc[nt][0] * inv0, oacc[nt][1] * inv0,
          oacc[nt][2] * inv1, oacc[nt][3] * inv1, oa);
      *reinterpret_cast<uint4*>(og + (h * 4 + nt) * 128) =
          make_uint4(oa[0], oa[1], oa[2], oa[3]);
    }
  }
}

// ============================ Kernel B ====================================
// out = O @ Wp + bp.  3 CTAs/SM.  A-frags streamed per-kt from scratch with
// manual double buffering (scratch read once per half); Wp staged once.
__global__ __launch_bounds__(256, 3)
void proj_kernel(const float* __restrict__ Wp, const float* __restrict__ bp,
                 float* __restrict__ out) {
  extern __shared__ uint32_t sm[];   // Wp, stride 136

  const int tid = threadIdx.x;
  const int lane = tid & 31;
  const int w = tid >> 5;
  const int g = lane >> 2;
  const int qi = lane & 3;
  const int b = blockIdx.x;
  const int row0 = w * 16 + g;
  const int row1 = row0 + 8;

  // stage Wp (tf32, stride 136)
  {
    const float4* wg = reinterpret_cast<const float4*>(Wp);
    #pragma unroll
    for (int i = 0; i < 16; i++) {
      int v = tid + i * 256;
      float4 f = wg[v];
      uint32_t* p = sm + (v >> 5) * PST + ((v & 31) << 2);
      p[0] = f2tf32(f.x); p[1] = f2tf32(f.y); p[2] = f2tf32(f.z); p[3] = f2tf32(f.w);
    }
  }
  __syncthreads();

  const uint32_t* ab = g_scratch + ((size_t)b * 8 + w) * 2048 + lane * 4;
  float* og = out + (size_t)b * 16384;

  #pragma unroll
  for (int half = 0; half < 2; half++) {
    float acc[8][4];
    #pragma unroll
    for (int nt8 = 0; nt8 < 8; nt8++) {
      int c = (half * 8 + nt8) * 8 + 2 * qi;
      float2 bp2 = *reinterpret_cast<const float2*>(bp + c);
      acc[nt8][0] = bp2.x; acc[nt8][1] = bp2.y; acc[nt8][2] = bp2.x; acc[nt8][3] = bp2.y;
    }
    // manual double buffer: A-frags per kt via LDG.128 (L2/DRAM served)
    uint4 a_next = *reinterpret_cast<const uint4*>(ab);
    #pragma unroll
    for (int kt = 0; kt < 16; kt++) {
      uint4 a_cur = a_next;
      if (kt < 15) a_next = *reinterpret_cast<const uint4*>(ab + (kt + 1) * 128);
      int brow = (kt * 8 + qi) * PST;
      #pragma unroll
      for (int nt8 = 0; nt8 < 8; nt8++) {
        int boff = brow + (half * 8 + nt8) * 8 + g;
        mma8(acc[nt8][0], acc[nt8][1], acc[nt8][2], acc[nt8][3],
             a_cur.x, a_cur.y, a_cur.z, a_cur.w,
             sm[boff], sm[boff + 4 * PST]);
      }
    }
    #pragma unroll
    for (int nt8 = 0; nt8 < 8; nt8++) {
      int c = (half * 8 + nt8) * 8 + 2 * qi;
      *reinterpret_cast<float2*>(og + row0 * 128 + c) = make_float2(acc[nt8][0], acc[nt8][1]);
      *reinterpret_cast<float2*>(og + row1 * 128 + c) = make_float2(acc[nt8][2], acc[nt8][3]);
    }
  }
}

}  // namespace

extern "C" void kernel_launch(void* const* d_in, const int* in_sizes, int n_in,
                              void* d_out, int out_size) {
  const float* x  = (const float*)d_in[0];
  const float* Wq = (const float*)d_in[1];
  const float* bq = (const float*)d_in[2];
  const float* Wk = (const float*)d_in[3];
  const float* bk = (const float*)d_in[4];
  const float* Wv = (const float*)d_in[5];
  const float* bv = (const float*)d_in[6];
  const float* Wp = (const float*)d_in[7];
  const float* bp = (const float*)d_in[8];
  float* out = (float*)d_out;

  int batches = in_sizes[0] / (128 * 128);  // 4096

  cudaFuncSetAttribute(qkv_attn_kernel,
                       cudaFuncAttributeMaxDynamicSharedMemorySize, SMEMA_BYTES);
  cudaFuncSetAttribute(proj_kernel,
                       cudaFuncAttributeMaxDynamicSharedMemorySize, SMEMB_BYTES);

  qkv_attn_kernel<<<batches, 256, SMEMA_BYTES>>>(x, Wq, bq, Wk, bk, Wv, bv);
  proj_kernel<<<batches, 256, SMEMB_BYTES>>>(Wp, bp, out);
}